// round 2
// baseline (speedup 1.0000x reference)
#include <cuda_runtime.h>
#include <cuda_bf16.h>

#define T_STEPS 128
#define N_RAYS_C 16384
#define NBLOCKS 2048

__global__ __launch_bounds__(128) void nerf_fp32_kernel(
    const float* __restrict__ rays_o, const float* __restrict__ rays_d,
    const float* __restrict__ tnoise, const float* __restrict__ aabb,
    const float* __restrict__ W1, const float* __restrict__ b1,
    const float* __restrict__ W2, const float* __restrict__ b2,
    const float* __restrict__ Wc1, const float* __restrict__ bc1,
    const float* __restrict__ Wc2, const float* __restrict__ bc2,
    float* __restrict__ out)
{
    // Weight tiles in smem, transposed + padded for float4 broadcast loads.
    __shared__ float4 sW1T4[64][7];    // W1T[j][k], k padded 27->28
    __shared__ float  sb1[64];
    __shared__ float4 sW2v[64][4];     // W2[j][c], c=16
    __shared__ float  sb2[16];
    __shared__ float4 sWc1T4[64][5];   // Wc1T[j][k], k padded 19->20
    __shared__ float  sbc1[64];
    __shared__ float4 sWc2v[64];       // Wc2[j][c], c padded 3->4
    __shared__ float  sbc2[4];
    __shared__ float  warpSum[4];
    __shared__ float  partial[4][4];

    const int tid  = threadIdx.x;
    const int lane = tid & 31;
    const int wid  = tid >> 5;

    // ---- stage weights ----
    {
        float* w1 = (float*)sW1T4;
        for (int i = tid; i < 64 * 28; i += 128) {
            int j = i / 28, k = i - j * 28;
            w1[i] = (k < 27) ? W1[k * 64 + j] : 0.0f;
        }
        float* w2 = (float*)sW2v;
        for (int i = tid; i < 64 * 16; i += 128) w2[i] = W2[i];
        float* wc1 = (float*)sWc1T4;
        for (int i = tid; i < 64 * 20; i += 128) {
            int j = i / 20, k = i - j * 20;
            wc1[i] = (k < 19) ? Wc1[k * 64 + j] : 0.0f;
        }
        float* wc2 = (float*)sWc2v;
        for (int i = tid; i < 64 * 4; i += 128) {
            int j = i >> 2, c = i & 3;
            wc2[i] = (c < 3) ? Wc2[j * 3 + c] : 0.0f;
        }
        if (tid < 64) sb1[tid]  = b1[tid];
        if (tid < 16) sb2[tid]  = b2[tid];
        if (tid >= 64 && tid < 128) sbc1[tid - 64] = bc1[tid - 64];
        if (tid >= 16 && tid < 20) sbc2[tid - 16] = (tid - 16 < 3) ? bc2[tid - 16] : 0.0f;
    }
    const float ax0 = aabb[0], ay0 = aabb[1], az0 = aabb[2];
    const float ax1 = aabb[3], ay1 = aabb[4], az1 = aabb[5];
    __syncthreads();

    for (int ray = blockIdx.x; ray < N_RAYS_C; ray += gridDim.x) {
        const float ox = rays_o[ray * 3 + 0], oy = rays_o[ray * 3 + 1], oz = rays_o[ray * 3 + 2];
        const float dx = rays_d[ray * 3 + 0], dy = rays_d[ray * 3 + 1], dz = rays_d[ray * 3 + 2];

        const float idx_ = 1.0f / dx, idy_ = 1.0f / dy, idz_ = 1.0f / dz;
        const float t0x = (ax0 - ox) * idx_, t1x = (ax1 - ox) * idx_;
        const float t0y = (ay0 - oy) * idy_, t1y = (ay1 - oy) * idy_;
        const float t0z = (az0 - oz) * idz_, t1z = (az1 - oz) * idz_;
        float tnear = fmaxf(fmaxf(fminf(t0x, t1x), fminf(t0y, t1y)), fminf(t0z, t1z));
        tnear = fmaxf(tnear, 0.0f);
        const float tfar = fminf(fminf(fmaxf(t0x, t1x), fmaxf(t0y, t1y)), fmaxf(t0z, t1z));

        if (!(tfar > tnear)) {   // block-uniform: all threads share the ray
            if (tid == 0) *(float4*)(out + ray * 4) = make_float4(0.f, 0.f, 0.f, 0.f);
            continue;
        }

        const float dnorm = sqrtf(dx * dx + dy * dy + dz * dz);
        const float idn = 1.0f / dnorm;
        const float dnx = dx * idn, dny = dy * idn, dnz = dz * idn;

        // sample positions
        const float n0 = tnoise[tid * N_RAYS_C + ray];
        const float n1 = (tid < 127) ? tnoise[(tid + 1) * N_RAYS_C + ray] : 0.0f;
        const float span = tfar - tnear;
        const float ts  = tnear + span * (((float)tid + n0) * (1.0f / 128.0f));
        const float ts1 = tnear + span * (((float)tid + 1.0f + n1) * (1.0f / 128.0f));
        const float delta = (tid < 127) ? (ts1 - ts) : (tfar * 10.0f - ts);

        const float px = ox + ts * dx, py = oy + ts * dy, pz = oz + ts * dz;
        const float xnx = 2.0f * (px - ax0) / (ax1 - ax0) - 1.0f;
        const float xny = 2.0f * (py - ay0) / (ay1 - ay0) - 1.0f;
        const float xnz = 2.0f * (pz - az0) / (az1 - az0) - 1.0f;

        // ---- positional encoding: 27 dims (+1 zero pad) ----
        float e[28];
        e[0] = xnx; e[1] = xny; e[2] = xnz;
        {
            float f = 3.14159265358979323846f;
            #pragma unroll
            for (int k = 0; k < 4; ++k) {
                float sx, cx, sy, cy, sz, cz;
                __sincosf(f * xnx, &sx, &cx);
                __sincosf(f * xny, &sy, &cy);
                __sincosf(f * xnz, &sz, &cz);
                e[3 + 6 * k + 0] = sx; e[3 + 6 * k + 1] = sy; e[3 + 6 * k + 2] = sz;
                e[6 + 6 * k + 0] = cx; e[6 + 6 * k + 1] = cy; e[6 + 6 * k + 2] = cz;
                f *= 2.0f;
            }
        }
        e[27] = 0.0f;

        // ---- layers 1+2 streamed: dh[16] = relu(e@W1+b1) @ W2 + b2 ----
        float dh[16];
        #pragma unroll
        for (int c = 0; c < 16; ++c) dh[c] = sb2[c];
        #pragma unroll 4
        for (int j = 0; j < 64; ++j) {
            float acc = sb1[j];
            #pragma unroll
            for (int q = 0; q < 7; ++q) {
                const float4 w = sW1T4[j][q];
                acc += e[4 * q + 0] * w.x + e[4 * q + 1] * w.y
                     + e[4 * q + 2] * w.z + e[4 * q + 3] * w.w;
            }
            const float hj = fmaxf(acc, 0.0f);
            #pragma unroll
            for (int q = 0; q < 4; ++q) {
                const float4 v = sW2v[j][q];
                dh[4 * q + 0] += hj * v.x;
                dh[4 * q + 1] += hj * v.y;
                dh[4 * q + 2] += hj * v.z;
                dh[4 * q + 3] += hj * v.w;
            }
        }
        const float sigma = __expf(dh[0]);

        // ---- color-net input: [feat(15), sh(4), pad] ----
        float in2[20];
        #pragma unroll
        for (int i = 0; i < 15; ++i) in2[i] = dh[i + 1];
        in2[15] = 0.28209479177387814f;
        in2[16] = 0.4886025119029199f * dny;
        in2[17] = 0.4886025119029199f * dnz;
        in2[18] = 0.4886025119029199f * dnx;
        in2[19] = 0.0f;

        // ---- layers 3+4 streamed ----
        float rgba0 = sbc2[0], rgba1 = sbc2[1], rgba2 = sbc2[2];
        #pragma unroll 4
        for (int j = 0; j < 64; ++j) {
            float acc = sbc1[j];
            #pragma unroll
            for (int q = 0; q < 5; ++q) {
                const float4 w = sWc1T4[j][q];
                acc += in2[4 * q + 0] * w.x + in2[4 * q + 1] * w.y
                     + in2[4 * q + 2] * w.z + in2[4 * q + 3] * w.w;
            }
            const float hj = fmaxf(acc, 0.0f);
            const float4 v = sWc2v[j];
            rgba0 += hj * v.x; rgba1 += hj * v.y; rgba2 += hj * v.z;
        }
        const float r = 1.0f / (1.0f + __expf(-rgba0));
        const float g = 1.0f / (1.0f + __expf(-rgba1));
        const float b = 1.0f / (1.0f + __expf(-rgba2));

        // ---- transmittance scan over T (128 threads = 128 samples) ----
        const float sd = sigma * delta * dnorm;
        float x = sd;
        #pragma unroll
        for (int off = 1; off < 32; off <<= 1) {
            float v = __shfl_up_sync(0xffffffffu, x, off);
            if (lane >= off) x += v;
        }
        if (lane == 31) warpSum[wid] = x;
        __syncthreads();
        float pre = 0.0f;
        #pragma unroll
        for (int w = 0; w < 4; ++w) if (w < wid) pre += warpSum[w];
        const float excl = (x + pre) - sd;           // exclusive prefix
        const float trans = __expf(-excl);
        const float alpha = 1.0f - __expf(-sd);
        const float wgt = trans * alpha;

        float cr = wgt * r, cg = wgt * g, cb = wgt * b, ca = wgt;
        #pragma unroll
        for (int off = 16; off > 0; off >>= 1) {
            cr += __shfl_xor_sync(0xffffffffu, cr, off);
            cg += __shfl_xor_sync(0xffffffffu, cg, off);
            cb += __shfl_xor_sync(0xffffffffu, cb, off);
            ca += __shfl_xor_sync(0xffffffffu, ca, off);
        }
        if (lane == 0) {
            partial[wid][0] = cr; partial[wid][1] = cg;
            partial[wid][2] = cb; partial[wid][3] = ca;
        }
        __syncthreads();
        if (tid == 0) {
            float4 o4;
            o4.x = partial[0][0] + partial[1][0] + partial[2][0] + partial[3][0];
            o4.y = partial[0][1] + partial[1][1] + partial[2][1] + partial[3][1];
            o4.z = partial[0][2] + partial[1][2] + partial[2][2] + partial[3][2];
            o4.w = partial[0][3] + partial[1][3] + partial[2][3] + partial[3][3];
            *(float4*)(out + ray * 4) = o4;
        }
        __syncthreads();   // protect scan scratch before next ray
    }
}

extern "C" void kernel_launch(void* const* d_in, const int* in_sizes, int n_in,
                              void* d_out, int out_size) {
    const float* rays_o = (const float*)d_in[0];
    const float* rays_d = (const float*)d_in[1];
    const float* tnoise = (const float*)d_in[2];
    const float* aabb   = (const float*)d_in[3];
    const float* W1     = (const float*)d_in[4];
    const float* b1     = (const float*)d_in[5];
    const float* W2     = (const float*)d_in[6];
    const float* b2     = (const float*)d_in[7];
    const float* Wc1    = (const float*)d_in[8];
    const float* bc1    = (const float*)d_in[9];
    const float* Wc2    = (const float*)d_in[10];
    const float* bc2    = (const float*)d_in[11];
    float* out = (float*)d_out;

    nerf_fp32_kernel<<<NBLOCKS, 128>>>(rays_o, rays_d, tnoise, aabb,
                                       W1, b1, W2, b2, Wc1, bc1, Wc2, bc2, out);
}

// round 3
// speedup vs baseline: 1.7025x; 1.7025x over previous
#include <cuda_runtime.h>
#include <cuda_bf16.h>

#define T_STEPS 128
#define N_RAYS_C 16384

typedef unsigned long long ull;

__device__ __forceinline__ ull ffma2(ull a, ull b, ull c) {
    ull d; asm("fma.rn.f32x2 %0, %1, %2, %3;" : "=l"(d) : "l"(a), "l"(b), "l"(c)); return d;
}
__device__ __forceinline__ ull add2(ull a, ull b) {
    ull d; asm("add.rn.f32x2 %0, %1, %2;" : "=l"(d) : "l"(a), "l"(b)); return d;
}
__device__ __forceinline__ ull pack2(float x) {
    ull d; unsigned r = __float_as_uint(x);
    asm("mov.b64 %0, {%1, %1};" : "=l"(d) : "r"(r)); return d;
}
__device__ __forceinline__ ull packf2(float lo, float hi) {
    ull d; asm("mov.b64 %0, {%1, %2};" : "=l"(d)
               : "r"(__float_as_uint(lo)), "r"(__float_as_uint(hi))); return d;
}
__device__ __forceinline__ float2 unpk(ull v) {
    unsigned lo, hi; asm("mov.b64 {%0, %1}, %2;" : "=r"(lo), "=r"(hi) : "l"(v));
    return make_float2(__uint_as_float(lo), __uint_as_float(hi));
}

struct Ray {
    float ox, oy, oz, dx, dy, dz;
    float tnear, tfar, span, dnorm, active;
};

__device__ __forceinline__ Ray mkray(const float* __restrict__ o, const float* __restrict__ d,
                                     int ray, float ax0, float ay0, float az0,
                                     float ax1, float ay1, float az1) {
    Ray r;
    r.ox = o[3 * ray + 0]; r.oy = o[3 * ray + 1]; r.oz = o[3 * ray + 2];
    r.dx = d[3 * ray + 0]; r.dy = d[3 * ray + 1]; r.dz = d[3 * ray + 2];
    const float ix = 1.0f / r.dx, iy = 1.0f / r.dy, iz = 1.0f / r.dz;
    const float t0x = (ax0 - r.ox) * ix, t1x = (ax1 - r.ox) * ix;
    const float t0y = (ay0 - r.oy) * iy, t1y = (ay1 - r.oy) * iy;
    const float t0z = (az0 - r.oz) * iz, t1z = (az1 - r.oz) * iz;
    float tn = fmaxf(fmaxf(fminf(t0x, t1x), fminf(t0y, t1y)), fminf(t0z, t1z));
    tn = fmaxf(tn, 0.0f);
    float tf = fminf(fminf(fmaxf(t0x, t1x), fmaxf(t0y, t1y)), fmaxf(t0z, t1z));
    if (tf > tn) { r.active = 1.0f; } else { r.active = 0.0f; tn = 0.0f; tf = 0.0f; }
    r.tnear = tn; r.tfar = tf; r.span = tf - tn;
    r.dnorm = sqrtf(r.dx * r.dx + r.dy * r.dy + r.dz * r.dz);
    return r;
}

__device__ __forceinline__ void posenc(float x, float y, float z, float* e) {
    e[0] = x; e[1] = y; e[2] = z;
    float f = 3.14159265358979323846f;
    #pragma unroll
    for (int k = 0; k < 4; ++k) {
        float sx, cx, sy, cy, sz, cz;
        __sincosf(f * x, &sx, &cx);
        __sincosf(f * y, &sy, &cy);
        __sincosf(f * z, &sz, &cz);
        e[3 + 6 * k + 0] = sx; e[3 + 6 * k + 1] = sy; e[3 + 6 * k + 2] = sz;
        e[6 + 6 * k + 0] = cx; e[6 + 6 * k + 1] = cy; e[6 + 6 * k + 2] = cz;
        f *= 2.0f;
    }
    e[27] = 0.0f;
}

__global__ __launch_bounds__(128) void nerf_f32x2_kernel(
    const float* __restrict__ rays_o, const float* __restrict__ rays_d,
    const float* __restrict__ tnoise, const float* __restrict__ aabb,
    const float* __restrict__ W1, const float* __restrict__ b1,
    const float* __restrict__ W2, const float* __restrict__ b2,
    const float* __restrict__ Wc1, const float* __restrict__ bc1,
    const float* __restrict__ Wc2, const float* __restrict__ bc2,
    float* __restrict__ out)
{
    // Weights k-major so adjacent output neurons are contiguous -> natural f32x2 pairs.
    __shared__ ulonglong2 sW1u[28][16];   // [k][jq]: (w_j,w_j+1),(w_j+2,w_j+3)
    __shared__ ulonglong2 sWc1u[20][16];
    __shared__ ulonglong2 sW2u[64][4];    // row j: 16 floats = 8 c-pairs
    __shared__ ulonglong2 sWc2u[64];      // row j: 4 floats (pad 3->4)
    __shared__ alignas(16) float sb1[64];
    __shared__ alignas(16) float sb2[16];
    __shared__ alignas(16) float sbc1[64];
    __shared__ alignas(16) float sbc2[4];
    __shared__ ull sWarp[4];
    __shared__ ull sPart[4][4];

    const int tid = threadIdx.x, lane = tid & 31, wid = tid >> 5;

    // ---- stage weights ----
    {
        float* f1 = (float*)sW1u;           // [28][64]
        for (int i = tid; i < 28 * 64; i += 128)
            f1[i] = (i < 27 * 64) ? W1[i] : 0.0f;
        float* f2 = (float*)sW2u;           // [64][16]
        for (int i = tid; i < 64 * 16; i += 128) f2[i] = W2[i];
        float* f3 = (float*)sWc1u;          // [20][64]
        for (int i = tid; i < 20 * 64; i += 128)
            f3[i] = (i < 19 * 64) ? Wc1[i] : 0.0f;
        float* f4 = (float*)sWc2u;          // [64][4]
        for (int i = tid; i < 64 * 4; i += 128) {
            int j = i >> 2, c = i & 3;
            f4[i] = (c < 3) ? Wc2[j * 3 + c] : 0.0f;
        }
        if (tid < 64) sb1[tid] = b1[tid];
        if (tid < 16) sb2[tid] = b2[tid];
        if (tid >= 64 && tid < 128) sbc1[tid - 64] = bc1[tid - 64];
        if (tid >= 16 && tid < 20) sbc2[tid - 16] = (tid - 16 < 3) ? bc2[tid - 16] : 0.0f;
    }
    const float ax0 = aabb[0], ay0 = aabb[1], az0 = aabb[2];
    const float ax1 = aabb[3], ay1 = aabb[4], az1 = aabb[5];
    __syncthreads();

    const int rayA = blockIdx.x * 2, rayB = rayA + 1;
    const Ray A = mkray(rays_o, rays_d, rayA, ax0, ay0, az0, ax1, ay1, az1);
    const Ray B = mkray(rays_o, rays_d, rayB, ax0, ay0, az0, ax1, ay1, az1);

    // sample positions + deltas (identical arithmetic to reference)
    const float nA0 = tnoise[tid * N_RAYS_C + rayA];
    const float nA1 = (tid < 127) ? tnoise[(tid + 1) * N_RAYS_C + rayA] : 0.0f;
    const float nB0 = tnoise[tid * N_RAYS_C + rayB];
    const float nB1 = (tid < 127) ? tnoise[(tid + 1) * N_RAYS_C + rayB] : 0.0f;

    const float tsA  = A.tnear + A.span * (((float)tid + nA0) * (1.0f / 128.0f));
    const float tsA1 = A.tnear + A.span * (((float)tid + 1.0f + nA1) * (1.0f / 128.0f));
    const float dltA = (tid < 127) ? (tsA1 - tsA) : (A.tfar * 10.0f - tsA);
    const float tsB  = B.tnear + B.span * (((float)tid + nB0) * (1.0f / 128.0f));
    const float tsB1 = B.tnear + B.span * (((float)tid + 1.0f + nB1) * (1.0f / 128.0f));
    const float dltB = (tid < 127) ? (tsB1 - tsB) : (B.tfar * 10.0f - tsB);

    float eA[28], eB[28];
    {
        const float pxA = A.ox + tsA * A.dx, pyA = A.oy + tsA * A.dy, pzA = A.oz + tsA * A.dz;
        posenc(2.0f * (pxA - ax0) / (ax1 - ax0) - 1.0f,
               2.0f * (pyA - ay0) / (ay1 - ay0) - 1.0f,
               2.0f * (pzA - az0) / (az1 - az0) - 1.0f, eA);
        const float pxB = B.ox + tsB * B.dx, pyB = B.oy + tsB * B.dy, pzB = B.oz + tsB * B.dz;
        posenc(2.0f * (pxB - ax0) / (ax1 - ax0) - 1.0f,
               2.0f * (pyB - ay0) / (ay1 - ay0) - 1.0f,
               2.0f * (pzB - az0) / (az1 - az0) - 1.0f, eB);
    }

    // ---- layers 1+2, streamed, f32x2 over output-neuron pairs ----
    ull dhA[8], dhB[8];
    #pragma unroll
    for (int c = 0; c < 8; ++c) {
        const ull bp = *(const ull*)&sb2[2 * c];
        dhA[c] = bp; dhB[c] = bp;
    }

    #pragma unroll 1
    for (int jq = 0; jq < 16; ++jq) {
        ull aA0 = *(const ull*)&sb1[4 * jq];
        ull aA1 = *(const ull*)&sb1[4 * jq + 2];
        ull aB0 = aA0, aB1 = aA1;
        #pragma unroll
        for (int k = 0; k < 28; ++k) {
            const ulonglong2 w = sW1u[k][jq];
            const ull pA = pack2(eA[k]);
            const ull pB = pack2(eB[k]);
            aA0 = ffma2(pA, w.x, aA0); aA1 = ffma2(pA, w.y, aA1);
            aB0 = ffma2(pB, w.x, aB0); aB1 = ffma2(pB, w.y, aB1);
        }
        const float2 hA01 = unpk(aA0), hA23 = unpk(aA1);
        const float2 hB01 = unpk(aB0), hB23 = unpk(aB1);
        const float hA[4] = { fmaxf(hA01.x, 0.f), fmaxf(hA01.y, 0.f),
                              fmaxf(hA23.x, 0.f), fmaxf(hA23.y, 0.f) };
        const float hB[4] = { fmaxf(hB01.x, 0.f), fmaxf(hB01.y, 0.f),
                              fmaxf(hB23.x, 0.f), fmaxf(hB23.y, 0.f) };
        #pragma unroll
        for (int jj = 0; jj < 4; ++jj) {
            const int j = 4 * jq + jj;
            const ulonglong2 w0 = sW2u[j][0], w1 = sW2u[j][1];
            const ulonglong2 w2v = sW2u[j][2], w3 = sW2u[j][3];
            const ull pA = pack2(hA[jj]);
            const ull pB = pack2(hB[jj]);
            dhA[0] = ffma2(pA, w0.x, dhA[0]); dhA[1] = ffma2(pA, w0.y, dhA[1]);
            dhA[2] = ffma2(pA, w1.x, dhA[2]); dhA[3] = ffma2(pA, w1.y, dhA[3]);
            dhA[4] = ffma2(pA, w2v.x, dhA[4]); dhA[5] = ffma2(pA, w2v.y, dhA[5]);
            dhA[6] = ffma2(pA, w3.x, dhA[6]); dhA[7] = ffma2(pA, w3.y, dhA[7]);
            dhB[0] = ffma2(pB, w0.x, dhB[0]); dhB[1] = ffma2(pB, w0.y, dhB[1]);
            dhB[2] = ffma2(pB, w1.x, dhB[2]); dhB[3] = ffma2(pB, w1.y, dhB[3]);
            dhB[4] = ffma2(pB, w2v.x, dhB[4]); dhB[5] = ffma2(pB, w2v.y, dhB[5]);
            dhB[6] = ffma2(pB, w3.x, dhB[6]); dhB[7] = ffma2(pB, w3.y, dhB[7]);
        }
    }

    // ---- sigma + color-net inputs ----
    float in2A[20], in2B[20];
    float sigmaA, sigmaB;
    {
        const float2 d0 = unpk(dhA[0]);
        sigmaA = __expf(d0.x);
        in2A[0] = d0.y;
        #pragma unroll
        for (int c = 1; c < 8; ++c) {
            const float2 t = unpk(dhA[c]);
            in2A[2 * c - 1] = t.x; in2A[2 * c] = t.y;
        }
        const float idn = 1.0f / A.dnorm;
        in2A[15] = 0.28209479177387814f;
        in2A[16] = 0.4886025119029199f * A.dy * idn;
        in2A[17] = 0.4886025119029199f * A.dz * idn;
        in2A[18] = 0.4886025119029199f * A.dx * idn;
        in2A[19] = 0.0f;
    }
    {
        const float2 d0 = unpk(dhB[0]);
        sigmaB = __expf(d0.x);
        in2B[0] = d0.y;
        #pragma unroll
        for (int c = 1; c < 8; ++c) {
            const float2 t = unpk(dhB[c]);
            in2B[2 * c - 1] = t.x; in2B[2 * c] = t.y;
        }
        const float idn = 1.0f / B.dnorm;
        in2B[15] = 0.28209479177387814f;
        in2B[16] = 0.4886025119029199f * B.dy * idn;
        in2B[17] = 0.4886025119029199f * B.dz * idn;
        in2B[18] = 0.4886025119029199f * B.dx * idn;
        in2B[19] = 0.0f;
    }

    // ---- layers 3+4, streamed ----
    ull cA01 = *(const ull*)&sbc2[0], cA23 = *(const ull*)&sbc2[2];
    ull cB01 = cA01, cB23 = cA23;

    #pragma unroll 1
    for (int jq = 0; jq < 16; ++jq) {
        ull aA0 = *(const ull*)&sbc1[4 * jq];
        ull aA1 = *(const ull*)&sbc1[4 * jq + 2];
        ull aB0 = aA0, aB1 = aA1;
        #pragma unroll
        for (int k = 0; k < 20; ++k) {
            const ulonglong2 w = sWc1u[k][jq];
            const ull pA = pack2(in2A[k]);
            const ull pB = pack2(in2B[k]);
            aA0 = ffma2(pA, w.x, aA0); aA1 = ffma2(pA, w.y, aA1);
            aB0 = ffma2(pB, w.x, aB0); aB1 = ffma2(pB, w.y, aB1);
        }
        const float2 hA01 = unpk(aA0), hA23 = unpk(aA1);
        const float2 hB01 = unpk(aB0), hB23 = unpk(aB1);
        const float hA[4] = { fmaxf(hA01.x, 0.f), fmaxf(hA01.y, 0.f),
                              fmaxf(hA23.x, 0.f), fmaxf(hA23.y, 0.f) };
        const float hB[4] = { fmaxf(hB01.x, 0.f), fmaxf(hB01.y, 0.f),
                              fmaxf(hB23.x, 0.f), fmaxf(hB23.y, 0.f) };
        #pragma unroll
        for (int jj = 0; jj < 4; ++jj) {
            const ulonglong2 w = sWc2u[4 * jq + jj];
            const ull pA = pack2(hA[jj]);
            const ull pB = pack2(hB[jj]);
            cA01 = ffma2(pA, w.x, cA01); cA23 = ffma2(pA, w.y, cA23);
            cB01 = ffma2(pB, w.x, cB01); cB23 = ffma2(pB, w.y, cB23);
        }
    }

    const float2 rgA = unpk(cA01); const float bAv = unpk(cA23).x;
    const float2 rgB = unpk(cB01); const float bBv = unpk(cB23).x;
    const float rA_ = 1.0f / (1.0f + __expf(-rgA.x));
    const float gA_ = 1.0f / (1.0f + __expf(-rgA.y));
    const float bA_ = 1.0f / (1.0f + __expf(-bAv));
    const float rB_ = 1.0f / (1.0f + __expf(-rgB.x));
    const float gB_ = 1.0f / (1.0f + __expf(-rgB.y));
    const float bB_ = 1.0f / (1.0f + __expf(-bBv));

    // ---- packed transmittance scan over T ----
    const float sdA = sigmaA * dltA * A.dnorm;
    const float sdB = sigmaB * dltB * B.dnorm;
    ull x = packf2(sdA, sdB);
    #pragma unroll
    for (int off = 1; off < 32; off <<= 1) {
        const ull v = __shfl_up_sync(0xffffffffu, x, off);
        if (lane >= off) x = add2(x, v);
    }
    if (lane == 31) sWarp[wid] = x;
    __syncthreads();
    ull pre = 0ULL;
    #pragma unroll
    for (int w = 0; w < 4; ++w) if (w < wid) pre = add2(pre, sWarp[w]);
    const float2 inc = unpk(add2(x, pre));
    const float transA = __expf(-(inc.x - sdA));
    const float transB = __expf(-(inc.y - sdB));
    const float alphaA = 1.0f - __expf(-sdA);
    const float alphaB = 1.0f - __expf(-sdB);
    const float wgtA = transA * alphaA * A.active;
    const float wgtB = transB * alphaB * B.active;

    ull c0 = packf2(wgtA * rA_, wgtB * rB_);
    ull c1 = packf2(wgtA * gA_, wgtB * gB_);
    ull c2 = packf2(wgtA * bA_, wgtB * bB_);
    ull c3 = packf2(wgtA, wgtB);
    #pragma unroll
    for (int off = 16; off > 0; off >>= 1) {
        c0 = add2(c0, __shfl_xor_sync(0xffffffffu, c0, off));
        c1 = add2(c1, __shfl_xor_sync(0xffffffffu, c1, off));
        c2 = add2(c2, __shfl_xor_sync(0xffffffffu, c2, off));
        c3 = add2(c3, __shfl_xor_sync(0xffffffffu, c3, off));
    }
    if (lane == 0) {
        sPart[wid][0] = c0; sPart[wid][1] = c1;
        sPart[wid][2] = c2; sPart[wid][3] = c3;
    }
    __syncthreads();
    if (tid == 0) {
        const ull t0 = add2(add2(sPart[0][0], sPart[1][0]), add2(sPart[2][0], sPart[3][0]));
        const ull t1 = add2(add2(sPart[0][1], sPart[1][1]), add2(sPart[2][1], sPart[3][1]));
        const ull t2 = add2(add2(sPart[0][2], sPart[1][2]), add2(sPart[2][2], sPart[3][2]));
        const ull t3 = add2(add2(sPart[0][3], sPart[1][3]), add2(sPart[2][3], sPart[3][3]));
        const float2 r2 = unpk(t0), g2 = unpk(t1), b2_ = unpk(t2), a2 = unpk(t3);
        *(float4*)(out + rayA * 4) = make_float4(r2.x, g2.x, b2_.x, a2.x);
        *(float4*)(out + rayB * 4) = make_float4(r2.y, g2.y, b2_.y, a2.y);
    }
}

extern "C" void kernel_launch(void* const* d_in, const int* in_sizes, int n_in,
                              void* d_out, int out_size) {
    const float* rays_o = (const float*)d_in[0];
    const float* rays_d = (const float*)d_in[1];
    const float* tnoise = (const float*)d_in[2];
    const float* aabb   = (const float*)d_in[3];
    const float* W1     = (const float*)d_in[4];
    const float* b1     = (const float*)d_in[5];
    const float* W2     = (const float*)d_in[6];
    const float* b2     = (const float*)d_in[7];
    const float* Wc1    = (const float*)d_in[8];
    const float* bc1    = (const float*)d_in[9];
    const float* Wc2    = (const float*)d_in[10];
    const float* bc2    = (const float*)d_in[11];
    float* out = (float*)d_out;

    nerf_f32x2_kernel<<<N_RAYS_C / 2, 128>>>(rays_o, rays_d, tnoise, aabb,
                                             W1, b1, W2, b2, Wc1, bc1, Wc2, bc2, out);
}

// round 4
// speedup vs baseline: 1.8680x; 1.0972x over previous
#include <cuda_runtime.h>
#include <cuda_bf16.h>

#define T_STEPS 128
#define N_RAYS_C 16384
#define R 4

typedef unsigned long long ull;

__device__ __forceinline__ ull ffma2(ull a, ull b, ull c) {
    ull d; asm("fma.rn.f32x2 %0, %1, %2, %3;" : "=l"(d) : "l"(a), "l"(b), "l"(c)); return d;
}
__device__ __forceinline__ ull add2(ull a, ull b) {
    ull d; asm("add.rn.f32x2 %0, %1, %2;" : "=l"(d) : "l"(a), "l"(b)); return d;
}
__device__ __forceinline__ ull pack2(float x) {
    ull d; unsigned r = __float_as_uint(x);
    asm("mov.b64 %0, {%1, %1};" : "=l"(d) : "r"(r)); return d;
}
__device__ __forceinline__ ull packf2(float lo, float hi) {
    ull d; asm("mov.b64 %0, {%1, %2};" : "=l"(d)
               : "r"(__float_as_uint(lo)), "r"(__float_as_uint(hi))); return d;
}
__device__ __forceinline__ float2 unpk(ull v) {
    unsigned lo, hi; asm("mov.b64 {%0, %1}, %2;" : "=r"(lo), "=r"(hi) : "l"(v));
    return make_float2(__uint_as_float(lo), __uint_as_float(hi));
}

__global__ __launch_bounds__(128) void nerf_f32x2_r4_kernel(
    const float* __restrict__ rays_o, const float* __restrict__ rays_d,
    const float* __restrict__ tnoise, const float* __restrict__ aabb,
    const float* __restrict__ W1, const float* __restrict__ b1,
    const float* __restrict__ W2, const float* __restrict__ b2,
    const float* __restrict__ Wc1, const float* __restrict__ bc1,
    const float* __restrict__ Wc2, const float* __restrict__ bc2,
    float* __restrict__ out)
{
    // Weights k-major: adjacent output neurons contiguous -> natural f32x2 pairs.
    __shared__ ulonglong2 sW1u[28][16];   // [k][jq]
    __shared__ ulonglong2 sWc1u[20][16];
    __shared__ ulonglong2 sW2u[64][4];    // row j: 16 floats
    __shared__ ulonglong2 sWc2u[64];      // row j: 4 floats (pad 3->4)
    __shared__ alignas(16) float sb1[64];
    __shared__ alignas(16) float sb2[16];
    __shared__ alignas(16) float sbc1[64];
    __shared__ alignas(16) float sbc2[4];
    __shared__ float sRayU[R][6];         // dnorm, active, shY, shZ, shX
    __shared__ ull sWarp[4][2];
    __shared__ ull sPart[4][8];

    const int tid = threadIdx.x, lane = tid & 31, wid = tid >> 5;

    // ---- stage weights ----
    {
        float* f1 = (float*)sW1u;           // [28][64]
        for (int i = tid; i < 28 * 64; i += 128)
            f1[i] = (i < 27 * 64) ? W1[i] : 0.0f;
        float* f2 = (float*)sW2u;           // [64][16]
        for (int i = tid; i < 64 * 16; i += 128) f2[i] = W2[i];
        float* f3 = (float*)sWc1u;          // [20][64]
        for (int i = tid; i < 20 * 64; i += 128)
            f3[i] = (i < 19 * 64) ? Wc1[i] : 0.0f;
        float* f4 = (float*)sWc2u;          // [64][4]
        for (int i = tid; i < 64 * 4; i += 128) {
            int j = i >> 2, c = i & 3;
            f4[i] = (c < 3) ? Wc2[j * 3 + c] : 0.0f;
        }
        if (tid < 64) sb1[tid] = b1[tid];
        if (tid < 16) sb2[tid] = b2[tid];
        if (tid >= 64 && tid < 128) sbc1[tid - 64] = bc1[tid - 64];
        if (tid >= 16 && tid < 20) sbc2[tid - 16] = (tid - 16 < 3) ? bc2[tid - 16] : 0.0f;
    }
    const float ax0 = aabb[0], ay0 = aabb[1], az0 = aabb[2];
    const float ax1 = aabb[3], ay1 = aabb[4], az1 = aabb[5];

    const int ray0 = blockIdx.x * R;

    // ---- per-ray setup: sampling + posenc ----
    float delta[R];
    float e[R][28];
    #pragma unroll
    for (int r = 0; r < R; ++r) {
        const int ray = ray0 + r;
        const float ox = rays_o[3 * ray + 0], oy = rays_o[3 * ray + 1], oz = rays_o[3 * ray + 2];
        const float dx = rays_d[3 * ray + 0], dy = rays_d[3 * ray + 1], dz = rays_d[3 * ray + 2];
        const float ix = 1.0f / dx, iy = 1.0f / dy, iz = 1.0f / dz;
        const float t0x = (ax0 - ox) * ix, t1x = (ax1 - ox) * ix;
        const float t0y = (ay0 - oy) * iy, t1y = (ay1 - oy) * iy;
        const float t0z = (az0 - oz) * iz, t1z = (az1 - oz) * iz;
        float tn = fmaxf(fmaxf(fminf(t0x, t1x), fminf(t0y, t1y)), fminf(t0z, t1z));
        tn = fmaxf(tn, 0.0f);
        float tf = fminf(fminf(fmaxf(t0x, t1x), fmaxf(t0y, t1y)), fmaxf(t0z, t1z));
        float act;
        if (tf > tn) { act = 1.0f; } else { act = 0.0f; tn = 0.0f; tf = 0.0f; }
        const float span = tf - tn;
        const float dnorm = sqrtf(dx * dx + dy * dy + dz * dz);

        if (tid == r) {
            const float idn = 1.0f / dnorm;
            sRayU[r][0] = dnorm;
            sRayU[r][1] = act;
            sRayU[r][2] = 0.4886025119029199f * dy * idn;
            sRayU[r][3] = 0.4886025119029199f * dz * idn;
            sRayU[r][4] = 0.4886025119029199f * dx * idn;
        }

        const float n0 = tnoise[tid * N_RAYS_C + ray];
        const float n1 = (tid < 127) ? tnoise[(tid + 1) * N_RAYS_C + ray] : 0.0f;
        const float ts  = tn + span * (((float)tid + n0) * (1.0f / 128.0f));
        const float ts1 = tn + span * (((float)tid + 1.0f + n1) * (1.0f / 128.0f));
        delta[r] = (tid < 127) ? (ts1 - ts) : (tf * 10.0f - ts);

        const float px = ox + ts * dx, py = oy + ts * dy, pz = oz + ts * dz;
        const float xnx = 2.0f * (px - ax0) / (ax1 - ax0) - 1.0f;
        const float xny = 2.0f * (py - ay0) / (ay1 - ay0) - 1.0f;
        const float xnz = 2.0f * (pz - az0) / (az1 - az0) - 1.0f;

        e[r][0] = xnx; e[r][1] = xny; e[r][2] = xnz;
        float f = 3.14159265358979323846f;
        #pragma unroll
        for (int k = 0; k < 4; ++k) {
            float sx, cx, sy, cy, sz, cz;
            __sincosf(f * xnx, &sx, &cx);
            __sincosf(f * xny, &sy, &cy);
            __sincosf(f * xnz, &sz, &cz);
            e[r][3 + 6 * k + 0] = sx; e[r][3 + 6 * k + 1] = sy; e[r][3 + 6 * k + 2] = sz;
            e[r][6 + 6 * k + 0] = cx; e[r][6 + 6 * k + 1] = cy; e[r][6 + 6 * k + 2] = cz;
            f *= 2.0f;
        }
        e[r][27] = 0.0f;
    }
    __syncthreads();   // weights + sRayU visible

    // ---- layers 1+2, streamed, f32x2 over output-neuron pairs, 4 rays ----
    ull dh[R][8];
    #pragma unroll
    for (int c = 0; c < 8; ++c) {
        const ull bp = *(const ull*)&sb2[2 * c];
        #pragma unroll
        for (int r = 0; r < R; ++r) dh[r][c] = bp;
    }

    #pragma unroll 1
    for (int jq = 0; jq < 16; ++jq) {
        const ull bb0 = *(const ull*)&sb1[4 * jq];
        const ull bb1 = *(const ull*)&sb1[4 * jq + 2];
        ull a0[R], a1[R];
        #pragma unroll
        for (int r = 0; r < R; ++r) { a0[r] = bb0; a1[r] = bb1; }
        #pragma unroll
        for (int k = 0; k < 28; ++k) {
            const ulonglong2 w = sW1u[k][jq];
            #pragma unroll
            for (int r = 0; r < R; ++r) {
                const ull p = pack2(e[r][k]);
                a0[r] = ffma2(p, w.x, a0[r]);
                a1[r] = ffma2(p, w.y, a1[r]);
            }
        }
        float h[R][4];
        #pragma unroll
        for (int r = 0; r < R; ++r) {
            const float2 h01 = unpk(a0[r]), h23 = unpk(a1[r]);
            h[r][0] = fmaxf(h01.x, 0.f); h[r][1] = fmaxf(h01.y, 0.f);
            h[r][2] = fmaxf(h23.x, 0.f); h[r][3] = fmaxf(h23.y, 0.f);
        }
        #pragma unroll
        for (int jj = 0; jj < 4; ++jj) {
            const int j = 4 * jq + jj;
            const ulonglong2 w0 = sW2u[j][0], w1 = sW2u[j][1];
            const ulonglong2 w2v = sW2u[j][2], w3 = sW2u[j][3];
            #pragma unroll
            for (int r = 0; r < R; ++r) {
                const ull p = pack2(h[r][jj]);
                dh[r][0] = ffma2(p, w0.x, dh[r][0]); dh[r][1] = ffma2(p, w0.y, dh[r][1]);
                dh[r][2] = ffma2(p, w1.x, dh[r][2]); dh[r][3] = ffma2(p, w1.y, dh[r][3]);
                dh[r][4] = ffma2(p, w2v.x, dh[r][4]); dh[r][5] = ffma2(p, w2v.y, dh[r][5]);
                dh[r][6] = ffma2(p, w3.x, dh[r][6]); dh[r][7] = ffma2(p, w3.y, dh[r][7]);
            }
        }
    }

    // ---- sigma + color-net inputs ----
    float in2[R][20];
    float sigma[R];
    #pragma unroll
    for (int r = 0; r < R; ++r) {
        const float2 d0 = unpk(dh[r][0]);
        sigma[r] = __expf(d0.x);
        in2[r][0] = d0.y;
        #pragma unroll
        for (int c = 1; c < 8; ++c) {
            const float2 t = unpk(dh[r][c]);
            in2[r][2 * c - 1] = t.x; in2[r][2 * c] = t.y;
        }
        in2[r][15] = 0.28209479177387814f;
        in2[r][16] = sRayU[r][2];
        in2[r][17] = sRayU[r][3];
        in2[r][18] = sRayU[r][4];
        in2[r][19] = 0.0f;
    }

    // ---- layers 3+4, streamed ----
    ull c01[R], c23[R];
    {
        const ull bc01 = *(const ull*)&sbc2[0];
        const ull bc23 = *(const ull*)&sbc2[2];
        #pragma unroll
        for (int r = 0; r < R; ++r) { c01[r] = bc01; c23[r] = bc23; }
    }

    #pragma unroll 1
    for (int jq = 0; jq < 16; ++jq) {
        const ull bb0 = *(const ull*)&sbc1[4 * jq];
        const ull bb1 = *(const ull*)&sbc1[4 * jq + 2];
        ull a0[R], a1[R];
        #pragma unroll
        for (int r = 0; r < R; ++r) { a0[r] = bb0; a1[r] = bb1; }
        #pragma unroll
        for (int k = 0; k < 20; ++k) {
            const ulonglong2 w = sWc1u[k][jq];
            #pragma unroll
            for (int r = 0; r < R; ++r) {
                const ull p = pack2(in2[r][k]);
                a0[r] = ffma2(p, w.x, a0[r]);
                a1[r] = ffma2(p, w.y, a1[r]);
            }
        }
        float h[R][4];
        #pragma unroll
        for (int r = 0; r < R; ++r) {
            const float2 h01 = unpk(a0[r]), h23 = unpk(a1[r]);
            h[r][0] = fmaxf(h01.x, 0.f); h[r][1] = fmaxf(h01.y, 0.f);
            h[r][2] = fmaxf(h23.x, 0.f); h[r][3] = fmaxf(h23.y, 0.f);
        }
        #pragma unroll
        for (int jj = 0; jj < 4; ++jj) {
            const ulonglong2 w = sWc2u[4 * jq + jj];
            #pragma unroll
            for (int r = 0; r < R; ++r) {
                const ull p = pack2(h[r][jj]);
                c01[r] = ffma2(p, w.x, c01[r]);
                c23[r] = ffma2(p, w.y, c23[r]);
            }
        }
    }

    float rC[R], gC[R], bC[R];
    #pragma unroll
    for (int r = 0; r < R; ++r) {
        const float2 rg = unpk(c01[r]);
        const float bv = unpk(c23[r]).x;
        rC[r] = 1.0f / (1.0f + __expf(-rg.x));
        gC[r] = 1.0f / (1.0f + __expf(-rg.y));
        bC[r] = 1.0f / (1.0f + __expf(-bv));
    }

    // ---- packed transmittance scans over T (AB pair, CD pair) ----
    float sd[R], wgt[R];
    #pragma unroll
    for (int r = 0; r < R; ++r) sd[r] = sigma[r] * delta[r] * sRayU[r][0];

    ull xAB = packf2(sd[0], sd[1]);
    ull xCD = packf2(sd[2], sd[3]);
    #pragma unroll
    for (int off = 1; off < 32; off <<= 1) {
        const ull vAB = __shfl_up_sync(0xffffffffu, xAB, off);
        const ull vCD = __shfl_up_sync(0xffffffffu, xCD, off);
        if (lane >= off) { xAB = add2(xAB, vAB); xCD = add2(xCD, vCD); }
    }
    if (lane == 31) { sWarp[wid][0] = xAB; sWarp[wid][1] = xCD; }
    __syncthreads();
    ull preAB = 0ULL, preCD = 0ULL;
    #pragma unroll
    for (int w = 0; w < 4; ++w) if (w < wid) {
        preAB = add2(preAB, sWarp[w][0]);
        preCD = add2(preCD, sWarp[w][1]);
    }
    const float2 incAB = unpk(add2(xAB, preAB));
    const float2 incCD = unpk(add2(xCD, preCD));
    const float inc[R] = { incAB.x, incAB.y, incCD.x, incCD.y };
    #pragma unroll
    for (int r = 0; r < R; ++r) {
        const float trans = __expf(-(inc[r] - sd[r]));
        const float alpha = 1.0f - __expf(-sd[r]);
        wgt[r] = trans * alpha * sRayU[r][1];
    }

    ull acc[4];   // r,g,b,a channels; lanes = (rayA,rayB) then reused for (C,D)
    acc[0] = packf2(wgt[0] * rC[0], wgt[1] * rC[1]);
    acc[1] = packf2(wgt[0] * gC[0], wgt[1] * gC[1]);
    acc[2] = packf2(wgt[0] * bC[0], wgt[1] * bC[1]);
    acc[3] = packf2(wgt[0],         wgt[1]);
    ull accCD[4];
    accCD[0] = packf2(wgt[2] * rC[2], wgt[3] * rC[3]);
    accCD[1] = packf2(wgt[2] * gC[2], wgt[3] * gC[3]);
    accCD[2] = packf2(wgt[2] * bC[2], wgt[3] * bC[3]);
    accCD[3] = packf2(wgt[2],         wgt[3]);
    #pragma unroll
    for (int off = 16; off > 0; off >>= 1) {
        #pragma unroll
        for (int ch = 0; ch < 4; ++ch) {
            acc[ch]   = add2(acc[ch],   __shfl_xor_sync(0xffffffffu, acc[ch],   off));
            accCD[ch] = add2(accCD[ch], __shfl_xor_sync(0xffffffffu, accCD[ch], off));
        }
    }
    if (lane == 0) {
        #pragma unroll
        for (int ch = 0; ch < 4; ++ch) {
            sPart[wid][ch]     = acc[ch];
            sPart[wid][4 + ch] = accCD[ch];
        }
    }
    __syncthreads();
    if (tid == 0) {
        ull tAB[4], tCD[4];
        #pragma unroll
        for (int ch = 0; ch < 4; ++ch) {
            tAB[ch] = add2(add2(sPart[0][ch], sPart[1][ch]),
                           add2(sPart[2][ch], sPart[3][ch]));
            tCD[ch] = add2(add2(sPart[0][4 + ch], sPart[1][4 + ch]),
                           add2(sPart[2][4 + ch], sPart[3][4 + ch]));
        }
        const float2 r2 = unpk(tAB[0]), g2 = unpk(tAB[1]), b2v = unpk(tAB[2]), a2 = unpk(tAB[3]);
        const float2 r4 = unpk(tCD[0]), g4 = unpk(tCD[1]), b4v = unpk(tCD[2]), a4 = unpk(tCD[3]);
        *(float4*)(out + (ray0 + 0) * 4) = make_float4(r2.x, g2.x, b2v.x, a2.x);
        *(float4*)(out + (ray0 + 1) * 4) = make_float4(r2.y, g2.y, b2v.y, a2.y);
        *(float4*)(out + (ray0 + 2) * 4) = make_float4(r4.x, g4.x, b4v.x, a4.x);
        *(float4*)(out + (ray0 + 3) * 4) = make_float4(r4.y, g4.y, b4v.y, a4.y);
    }
}

extern "C" void kernel_launch(void* const* d_in, const int* in_sizes, int n_in,
                              void* d_out, int out_size) {
    const float* rays_o = (const float*)d_in[0];
    const float* rays_d = (const float*)d_in[1];
    const float* tnoise = (const float*)d_in[2];
    const float* aabb   = (const float*)d_in[3];
    const float* W1     = (const float*)d_in[4];
    const float* b1     = (const float*)d_in[5];
    const float* W2     = (const float*)d_in[6];
    const float* b2     = (const float*)d_in[7];
    const float* Wc1    = (const float*)d_in[8];
    const float* bc1    = (const float*)d_in[9];
    const float* Wc2    = (const float*)d_in[10];
    const float* bc2    = (const float*)d_in[11];
    float* out = (float*)d_out;

    nerf_f32x2_r4_kernel<<<N_RAYS_C / R, 128>>>(rays_o, rays_d, tnoise, aabb,
                                                W1, b1, W2, b2, Wc1, bc1, Wc2, bc2, out);
}